// round 7
// baseline (speedup 1.0000x reference)
#include <cuda_runtime.h>

// VectorQuantizer on GB300 (sm_103a).  [design converged R5; awaiting first bench]
// Inputs:  d_in[0] = inputs  [16,1024,512] f32   (N = 16384 rows, D = 512)
//          d_in[1] = embedding [8192,512]  f32   (K = 8192 codes)
// Output layout (float32, concatenated in reference return order):
//   [0 : NE)            quantized_ste  (numerically == quantized)
//   [NE : 2NE)          quantized
//   [2NE]               q_loss
//   [2NE+1]             e_loss
//   [2NE+2 : +nrows)    indices (as float)
//
// Numerics contract: distance = fl(fl(|x|^2 + |e|^2) - 2*dot), dot accumulated
// in fp32 sequentially over d ascending (single FMA chain; fma.rn.f32x2 is
// lanewise rn-fp32, bit-identical to scalar FFMA chain). Argmin ties go to the
// lowest code index (jnp.argmin) — ~6% of rows are decided by the tie-break,
// so every reduction here is lexicographic (value, index). K is range-split
// across 16 CTA groups and merged lexicographically == exact full-range argmin.

#define DIMS 512
#define MAXN 16384
#define MAXK 8192

#define TM 128    // rows per CTA tile
#define TK 128    // codes per k-tile
#define TD 16     // depth chunk
#define KSPLIT 16 // K ranges; grid = 128 x 16 = 2048 CTAs (6.92 waves @ occ 2)

#define XS_STRIDE 132   // floats; 528 B row stride (16B-aligned)

typedef unsigned long long u64;

__device__ float g_xnorm[MAXN];
__device__ float g_enorm[MAXK];
__device__ float g_bestv[KSPLIT * MAXN];
__device__ int   g_besti[KSPLIT * MAXN];
__device__ int   g_best[MAXN];
__device__ float g_losspart[MAXN];

// ---------------------------------------------------------------------------
// Row squared-norms. One block per row, 128 threads x float4.
// ---------------------------------------------------------------------------
__global__ void row_norm_kernel(const float* __restrict__ src, int which)
{
    int row = blockIdx.x;
    const float4 v = reinterpret_cast<const float4*>(src + (size_t)row * DIMS)[threadIdx.x];
    float s = v.x * v.x + v.y * v.y + v.z * v.z + v.w * v.w;

    __shared__ float sm[128];
    sm[threadIdx.x] = s;
    __syncthreads();
    #pragma unroll
    for (int off = 64; off > 0; off >>= 1) {
        if (threadIdx.x < off) sm[threadIdx.x] += sm[threadIdx.x + off];
        __syncthreads();
    }
    if (threadIdx.x == 0) {
        if (which) g_enorm[row] = sm[0];
        else       g_xnorm[row] = sm[0];
    }
}

// ---------------------------------------------------------------------------
// Fused distance + per-K-range argmin.
// Grid: (nrows/TM, KSPLIT). CTA: 256 threads = 16(tr) x 16(tc).
// Thread tile: 8 rows x 8 codes as 8x4 packed f32x2 accumulators (FFMA2);
// the 4 FFMA2 sharing one a2 splat are consecutive so ptxas can .reuse a2
// (keeps RF-bank distinct count at 2 -> rt 2). Double-buffered smem, ONE
// barrier per chunk. Tiles stored TRANSPOSED ([d][row/code]); b code-pairs
// load directly as u64. Running argmin state lives in smem (regs ~108).
// ---------------------------------------------------------------------------
__global__ __launch_bounds__(256, 2)
void dist_argmin_kernel(const float* __restrict__ X, const float* __restrict__ E, int K)
{
    __shared__ __align__(16) float Xs[2][TD][XS_STRIDE];
    __shared__ __align__(16) float Es[2][TD][XS_STRIDE];
    __shared__ float bvs[8][256];   // running best value per (i, thread)
    __shared__ int   bis[8][256];   // running best index per (i, thread)

    const int tid = threadIdx.x;
    const int tr  = tid >> 4;        // 0..15 -> row group (8 rows)
    const int tc  = tid & 15;        // 0..15 -> code group (8 codes)
    const int rowBase = blockIdx.x * TM;

    const int kRange = K / KSPLIT;                    // 512
    const int kBase  = blockIdx.y * kRange;
    const int nChunk = (kRange / TK) * (DIMS / TD);   // 4 * 32 = 128

    // loader mapping: each thread loads rows fr and fr+64, depth quad fq
    const int fr = tid >> 2;        // 0..63
    const int fq = tid & 3;         // 0..3  -> d offset fq*4 .. fq*4+3

    #pragma unroll
    for (int i = 0; i < 8; i++) {
        bvs[i][tid] = 3.402823466e38f;
        bis[i][tid] = 0x7fffffff;
    }

    // packed accumulators: acc2[i][j2] holds codes (tc*8+2*j2, tc*8+2*j2+1)
    u64 acc2[8][4];
    #pragma unroll
    for (int i = 0; i < 8; i++)
        #pragma unroll
        for (int j = 0; j < 4; j++) acc2[i][j] = 0ull;   // two +0.0f

    // ---- prefetch chunk 0 and store into buffer 0 ----
    float4 px0, px1, pe0, pe1;
    px0 = *reinterpret_cast<const float4*>(&X[(size_t)(rowBase + fr)      * DIMS + fq * 4]);
    px1 = *reinterpret_cast<const float4*>(&X[(size_t)(rowBase + fr + 64) * DIMS + fq * 4]);
    pe0 = *reinterpret_cast<const float4*>(&E[(size_t)(kBase + fr)        * DIMS + fq * 4]);
    pe1 = *reinterpret_cast<const float4*>(&E[(size_t)(kBase + fr + 64)   * DIMS + fq * 4]);
    {
        Xs[0][fq * 4 + 0][fr] = px0.x;  Xs[0][fq * 4 + 1][fr] = px0.y;
        Xs[0][fq * 4 + 2][fr] = px0.z;  Xs[0][fq * 4 + 3][fr] = px0.w;
        Xs[0][fq * 4 + 0][fr + 64] = px1.x;  Xs[0][fq * 4 + 1][fr + 64] = px1.y;
        Xs[0][fq * 4 + 2][fr + 64] = px1.z;  Xs[0][fq * 4 + 3][fr + 64] = px1.w;
        Es[0][fq * 4 + 0][fr] = pe0.x;  Es[0][fq * 4 + 1][fr] = pe0.y;
        Es[0][fq * 4 + 2][fr] = pe0.z;  Es[0][fq * 4 + 3][fr] = pe0.w;
        Es[0][fq * 4 + 0][fr + 64] = pe1.x;  Es[0][fq * 4 + 1][fr + 64] = pe1.y;
        Es[0][fq * 4 + 2][fr + 64] = pe1.z;  Es[0][fq * 4 + 3][fr + 64] = pe1.w;
    }

    for (int c = 0; c < nChunk; c++) {
        __syncthreads();              // buf[c&1] ready; buf[(c+1)&1] free
        const int p = c & 1;

        // prefetch chunk c+1 (latency hidden behind ~4k cycles of math)
        if (c + 1 < nChunk) {
            const int nc = c + 1;
            const int kt = nc >> 5;                 // k-tile of next chunk
            const int dc = (nc & 31) * TD;          // depth offset of next chunk
            px0 = *reinterpret_cast<const float4*>(&X[(size_t)(rowBase + fr)      * DIMS + dc + fq * 4]);
            px1 = *reinterpret_cast<const float4*>(&X[(size_t)(rowBase + fr + 64) * DIMS + dc + fq * 4]);
            pe0 = *reinterpret_cast<const float4*>(&E[(size_t)(kBase + kt * TK + fr)      * DIMS + dc + fq * 4]);
            pe1 = *reinterpret_cast<const float4*>(&E[(size_t)(kBase + kt * TK + fr + 64) * DIMS + dc + fq * 4]);
        }

        // ---- compute chunk c: 16 d-steps of 32 FFMA2 ----
        #pragma unroll
        for (int d = 0; d < TD; d++) {
            const uint4 a0 = *reinterpret_cast<const uint4*>(&Xs[p][d][tr * 8]);
            const uint4 a1 = *reinterpret_cast<const uint4*>(&Xs[p][d][tr * 8 + 4]);
            const ulonglong2 b01 = *reinterpret_cast<const ulonglong2*>(&Es[p][d][tc * 8]);
            const ulonglong2 b23 = *reinterpret_cast<const ulonglong2*>(&Es[p][d][tc * 8 + 4]);
            const u64 bb0 = b01.x, bb1 = b01.y, bb2 = b23.x, bb3 = b23.y;
            const unsigned aw[8] = {a0.x, a0.y, a0.z, a0.w, a1.x, a1.y, a1.z, a1.w};
            #pragma unroll
            for (int i = 0; i < 8; i++) {
                u64 a2;
                asm("mov.b64 %0, {%1, %1};" : "=l"(a2) : "r"(aw[i]));
                // 4 consecutive FFMA2 sharing a2 -> operand reuse, rt 2
                asm("fma.rn.f32x2 %0, %1, %2, %0;" : "+l"(acc2[i][0]) : "l"(a2), "l"(bb0));
                asm("fma.rn.f32x2 %0, %1, %2, %0;" : "+l"(acc2[i][1]) : "l"(a2), "l"(bb1));
                asm("fma.rn.f32x2 %0, %1, %2, %0;" : "+l"(acc2[i][2]) : "l"(a2), "l"(bb2));
                asm("fma.rn.f32x2 %0, %1, %2, %0;" : "+l"(acc2[i][3]) : "l"(a2), "l"(bb3));
            }
        }

        // ---- store chunk c+1 into the other buffer ----
        if (c + 1 < nChunk) {
            const int q = p ^ 1;
            Xs[q][fq * 4 + 0][fr] = px0.x;  Xs[q][fq * 4 + 1][fr] = px0.y;
            Xs[q][fq * 4 + 2][fr] = px0.z;  Xs[q][fq * 4 + 3][fr] = px0.w;
            Xs[q][fq * 4 + 0][fr + 64] = px1.x;  Xs[q][fq * 4 + 1][fr + 64] = px1.y;
            Xs[q][fq * 4 + 2][fr + 64] = px1.z;  Xs[q][fq * 4 + 3][fr + 64] = px1.w;
            Es[q][fq * 4 + 0][fr] = pe0.x;  Es[q][fq * 4 + 1][fr] = pe0.y;
            Es[q][fq * 4 + 2][fr] = pe0.z;  Es[q][fq * 4 + 3][fr] = pe0.w;
            Es[q][fq * 4 + 0][fr + 64] = pe1.x;  Es[q][fq * 4 + 1][fr + 64] = pe1.y;
            Es[q][fq * 4 + 2][fr + 64] = pe1.z;  Es[q][fq * 4 + 3][fr + 64] = pe1.w;
        }

        // ---- k-tile epilogue: distances + argmin (runs 4x per kernel) ----
        if ((c & 31) == 31) {
            const int kt = c >> 5;
            #pragma unroll
            for (int i = 0; i < 8; i++) {
                const float xnv = g_xnorm[rowBase + tr * 8 + i];
                float lv = 3.402823466e38f;
                int   li = 0x7fffffff;
                #pragma unroll
                for (int j2 = 0; j2 < 4; j2++) {    // ascending code order
                    float dlo, dhi;
                    asm("mov.b64 {%0, %1}, %2;" : "=f"(dlo), "=f"(dhi) : "l"(acc2[i][j2]));
                    const int c0 = kBase + kt * TK + tc * 8 + 2 * j2;
                    float en0 = g_enorm[c0];
                    float en1 = g_enorm[c0 + 1];
                    // exact reference rounding: fl(fl(xn+en) - 2*dot)
                    float d0 = __fsub_rn(__fadd_rn(xnv, en0), 2.0f * dlo);
                    float d1 = __fsub_rn(__fadd_rn(xnv, en1), 2.0f * dhi);
                    if (d0 < lv) { lv = d0; li = c0; }       // first-min kept
                    if (d1 < lv) { lv = d1; li = c0 + 1; }
                }
                // lex-min over the 16 tc lanes (offsets < 16 stay in the group)
                #pragma unroll
                for (int off = 1; off < 16; off <<= 1) {
                    float ov = __shfl_xor_sync(0xffffffffu, lv, off);
                    int   oi = __shfl_xor_sync(0xffffffffu, li, off);
                    if (ov < lv || (ov == lv && oi < li)) { lv = ov; li = oi; }
                }
                float pv = bvs[i][tid];
                int   pi = bis[i][tid];
                if (lv < pv || (lv == pv && li < pi)) { bvs[i][tid] = lv; bis[i][tid] = li; }
            }
            #pragma unroll
            for (int i = 0; i < 8; i++)
                #pragma unroll
                for (int j = 0; j < 4; j++) acc2[i][j] = 0ull;
        }
    }

    if (tc == 0) {
        #pragma unroll
        for (int i = 0; i < 8; i++) {
            int row = rowBase + tr * 8 + i;
            g_bestv[blockIdx.y * MAXN + row] = bvs[i][tid];
            g_besti[blockIdx.y * MAXN + row] = bis[i][tid];
        }
    }
}

// ---------------------------------------------------------------------------
// Merge K-ranges + gather + STE + loss partials. One block (128 thr) per row.
// ---------------------------------------------------------------------------
__global__ void gather_out_kernel(const float* __restrict__ X, const float* __restrict__ E,
                                  float* __restrict__ out, long long NE, long long outsz)
{
    int row = blockIdx.x;

    // exact lex-min merge of the KSPLIT per-range winners (ranges ascending in k)
    float bvv = 3.402823466e38f;
    int   idx = 0x7fffffff;
    #pragma unroll
    for (int h = 0; h < KSPLIT; h++) {
        float v = g_bestv[h * MAXN + row];
        int   i = g_besti[h * MAXN + row];
        if (v < bvv || (v == bvv && i < idx)) { bvv = v; idx = i; }
    }
    if (threadIdx.x == 0) g_best[row] = idx;

    float4 x = reinterpret_cast<const float4*>(X + (size_t)row * DIMS)[threadIdx.x];
    float4 e = reinterpret_cast<const float4*>(E + (size_t)idx * DIMS)[threadIdx.x];

    float4 df, st;
    df.x = __fsub_rn(e.x, x.x); st.x = __fadd_rn(x.x, df.x);
    df.y = __fsub_rn(e.y, x.y); st.y = __fadd_rn(x.y, df.y);
    df.z = __fsub_rn(e.z, x.z); st.z = __fadd_rn(x.z, df.z);
    df.w = __fsub_rn(e.w, x.w); st.w = __fadd_rn(x.w, df.w);

    long long base = (long long)row * DIMS + (long long)threadIdx.x * 4;
    if (base + 3 < outsz)
        *reinterpret_cast<float4*>(out + base) = st;
    if (NE + base + 3 < outsz)
        *reinterpret_cast<float4*>(out + NE + base) = e;

    float s = __fmul_rn(df.x, df.x) + __fmul_rn(df.y, df.y)
            + __fmul_rn(df.z, df.z) + __fmul_rn(df.w, df.w);

    __shared__ float sm[128];
    sm[threadIdx.x] = s;
    __syncthreads();
    #pragma unroll
    for (int off = 64; off > 0; off >>= 1) {
        if (threadIdx.x < off) sm[threadIdx.x] += sm[threadIdx.x + off];
        __syncthreads();
    }
    if (threadIdx.x == 0) g_losspart[row] = sm[0];
}

// ---------------------------------------------------------------------------
// Final reduce (deterministic, double accumulation) + losses + indices + tail.
// ---------------------------------------------------------------------------
__global__ void finalize_kernel(float* __restrict__ out, int nrows, long long NE, long long outsz)
{
    __shared__ double sm[256];
    double s = 0.0;
    for (int i = threadIdx.x; i < nrows; i += 256) s += (double)g_losspart[i];
    sm[threadIdx.x] = s;
    __syncthreads();
    #pragma unroll
    for (int off = 128; off > 0; off >>= 1) {
        if (threadIdx.x < off) sm[threadIdx.x] += sm[threadIdx.x + off];
        __syncthreads();
    }
    if (threadIdx.x == 0) {
        float loss = (float)(sm[0] / (double)NE);
        if (2 * NE     < outsz) out[2 * NE]     = loss;  // q_loss
        if (2 * NE + 1 < outsz) out[2 * NE + 1] = loss;  // e_loss (identical value)
    }
    for (int i = threadIdx.x; i < nrows; i += 256) {
        long long o = 2 * NE + 2 + i;
        if (o < outsz) out[o] = (float)g_best[i];
    }
    for (long long o = 2 * NE + 2 + nrows + threadIdx.x; o < outsz; o += 256)
        out[o] = 0.0f;
}

// ---------------------------------------------------------------------------
extern "C" void kernel_launch(void* const* d_in, const int* in_sizes, int n_in,
                              void* d_out, int out_size)
{
    const float* X = (const float*)d_in[0];   // inputs
    const float* E = (const float*)d_in[1];   // embedding

    const long long NE = (long long)in_sizes[0];      // 8388608
    const int nrows    = (int)(NE / DIMS);            // 16384
    const int K        = in_sizes[1] / DIMS;          // 8192
    float* out         = (float*)d_out;
    const long long outsz = (long long)out_size;

    row_norm_kernel<<<nrows, 128>>>(X, 0);
    row_norm_kernel<<<K,     128>>>(E, 1);

    dim3 grid(nrows / TM, KSPLIT);
    dist_argmin_kernel<<<grid, 256>>>(X, E, K);

    gather_out_kernel<<<nrows, 128>>>(X, E, out, NE, outsz);
    finalize_kernel<<<1, 256>>>(out, nrows, NE, outsz);
}